// round 9
// baseline (speedup 1.0000x reference)
#include <cuda_runtime.h>
#include <cuda_fp16.h>
#include <math.h>

#define DIMZ 128
#define HW   (128*128)
#define VOL  (128*128*128)
#define NB   2
#define NK   4
#define RAD  4
#define ZC   8                  // z-chunk in K2
#define K2_CTAS (16*16*8)       // ytiles * zchunks * (k*b)

// 32 MB fp16 scratch for the XY-blurred labels field.
__device__ __align__(16) __half g_blur[NB*NK*VOL];

struct Scal {
    float  S1[NB*NK];
    float  S2[NB*NK];
    double num[NK];
    double den[NK];
    int    ctr;
};
__device__ Scal g_s;

// gauss taps: exp(-x^2/(2*25)) for x=-4..4 (fp32, for x-blur + packing)
__constant__ float c_g[9] = {
    0.72614904f, 0.83527021f, 0.92311635f, 0.98019867f, 1.0f,
    0.98019867f, 0.92311635f, 0.83527021f, 0.72614904f
};
// same taps as packed half2 bit patterns (round-to-nearest fp16)
__constant__ unsigned c_gh2[9] = {
    0x39CF39CFu, 0x3AAF3AAFu, 0x3B633B63u, 0x3BD73BD7u, 0x3C003C00u,
    0x3BD73BD7u, 0x3B633B63u, 0x3AAF3AAFu, 0x39CF39CFu
};

__device__ __forceinline__ __half2 u2h(unsigned u) {
    return *reinterpret_cast<__half2*>(&u);
}
__device__ __forceinline__ unsigned h2u(__half2 h) {
    return *reinterpret_cast<unsigned*>(&h);
}

__device__ __forceinline__ float blur9(const float* a) {
    float acc = 0.f;
    #pragma unroll
    for (int t = 0; t < 9; t++) acc = fmaf(c_g[t], a[t], acc);
    return acc;
}

// Load labels row gy (zero outside volume), accumulate mean sums on uniquely
// owned center rows, return the X-blurred float4 for this lane (x = 4*lane)
// using lane shuffles for the +-4 halo. No shared memory.
__device__ __forceinline__ float4 xblur_load(
    int gy, const float4* __restrict__ lp4, const float4* __restrict__ ip4,
    int lane, int y0, float& s1, float& s2)
{
    float4 c = make_float4(0.f, 0.f, 0.f, 0.f);
    if (gy >= 0 && gy < 128) {
        c = __ldcs(lp4 + gy * 32 + lane);
        if (gy >= y0 && gy < y0 + 32) {
            float4 u = ip4[gy * 32 + lane];
            s1 += c.x*u.x + c.y*u.y + c.z*u.z + c.w*u.w;
            s2 += c.x + c.y + c.z + c.w;
        }
    }
    float a[12];
    a[0] = __shfl_up_sync(0xffffffffu, c.x, 1);
    a[1] = __shfl_up_sync(0xffffffffu, c.y, 1);
    a[2] = __shfl_up_sync(0xffffffffu, c.z, 1);
    a[3] = __shfl_up_sync(0xffffffffu, c.w, 1);
    if (lane == 0) { a[0] = a[1] = a[2] = a[3] = 0.f; }
    a[4] = c.x; a[5] = c.y; a[6] = c.z; a[7] = c.w;
    a[8]  = __shfl_down_sync(0xffffffffu, c.x, 1);
    a[9]  = __shfl_down_sync(0xffffffffu, c.y, 1);
    a[10] = __shfl_down_sync(0xffffffffu, c.z, 1);
    a[11] = __shfl_down_sync(0xffffffffu, c.w, 1);
    if (lane == 31) { a[8] = a[9] = a[10] = a[11] = 0.f; }
    float4 r;
    r.x = blur9(a + 0);
    r.y = blur9(a + 1);
    r.z = blur9(a + 2);
    r.w = blur9(a + 3);
    return r;
}

// Pack an fp32 x-blurred float4 into 2 half2 (uint2).
__device__ __forceinline__ uint2 pack4(float4 r) {
    uint2 p;
    p.x = h2u(__floats2half2_rn(r.x, r.y));
    p.y = h2u(__floats2half2_rn(r.z, r.w));
    return p;
}

// ---------------------------------------------------------------------------
// K1: XY blur of labels, register/shuffle resident. Y-ring held as packed
// half2; Y-blur in HFMA2.  (R6 body — best measured.)
// grid: (64 zpairs, 4 k, 2 b) x 256 thr; warp w -> z = 2*zg + (w>>2), yq = w&3.
// Fused: mean sums (sum p*inp, sum p) per (b,k).
// ---------------------------------------------------------------------------
__global__ __launch_bounds__(256)
void k_xyblur(const float* __restrict__ labels, const float* __restrict__ inputs) {
    const int tid = threadIdx.x;
    const int warp = tid >> 5, lane = tid & 31;
    const int z  = blockIdx.x * 2 + (warp >> 2);
    const int yq = warp & 3;
    const int y0 = yq * 32;
    const int k  = blockIdx.y;
    const int b  = blockIdx.z;
    const int x4 = lane * 4;

    const float4* lp4 = (const float4*)(labels + (size_t)(b*NK + k) * VOL + (size_t)z * HW);
    const float4* ip4 = (const float4*)(inputs + (size_t)b * VOL + (size_t)z * HW);
    __half* op = g_blur + (size_t)(b*NK + k) * VOL + (size_t)z * HW;

    float s1 = 0.f, s2 = 0.f;
    uint2 w[9];
    #pragma unroll
    for (int j = 0; j < 9; j++)
        w[j] = pack4(xblur_load(y0 - RAD + j, lp4, ip4, lane, y0, s1, s2));

    #pragma unroll 4
    for (int i = 0; i < 32; i++) {
        __half2 b0 = u2h(0u), b1 = u2h(0u);
        #pragma unroll
        for (int j = 0; j < 9; j++) {
            __half2 g = u2h(c_gh2[j]);
            b0 = __hfma2(g, u2h(w[j].x), b0);
            b1 = __hfma2(g, u2h(w[j].y), b1);
        }
        uint2 pk; pk.x = h2u(b0); pk.y = h2u(b1);
        *reinterpret_cast<uint2*>(op + (y0 + i) * 128 + x4) = pk;

        #pragma unroll
        for (int j = 0; j < 8; j++) w[j] = w[j + 1];
        w[8] = pack4(xblur_load(y0 + i + RAD + 1, lp4, ip4, lane, y0, s1, s2));
    }

    // Warp-reduce mean sums, then CTA-reduce -> 2 atomics per CTA.
    #pragma unroll
    for (int o = 16; o; o >>= 1) {
        s1 += __shfl_down_sync(0xffffffffu, s1, o);
        s2 += __shfl_down_sync(0xffffffffu, s2, o);
    }
    __shared__ float rs1[8], rs2[8];
    if (lane == 0) { rs1[warp] = s1; rs2[warp] = s2; }
    __syncthreads();
    if (tid == 0) {
        float a = 0.f, c = 0.f;
        #pragma unroll
        for (int ww = 0; ww < 8; ww++) { a += rs1[ww]; c += rs2[ww]; }
        atomicAdd(&g_s.S1[b*NK + k], a);
        atomicAdd(&g_s.S2[b*NK + k], c);
    }
}

// ---------------------------------------------------------------------------
// K2: Z blur with rolling half2 window (HFMA2), fused weights + reduction.
//     num = sum B(p)*p*w,  den = sum B(p)*w   (blur operator self-adjoint).
// R6 body; levers: 5 CTAs/SM (launch_bounds) + ZC=8 (2048 CTAs, finer tail).
// grid: (16 ytiles, 16 zchunks, 8 = k + 4*b) x 256. Last CTA finalizes.
// ---------------------------------------------------------------------------
__global__ __launch_bounds__(256, 5)
void k_zred(const float* __restrict__ labels, const float* __restrict__ inputs,
            float* __restrict__ out) {
    const int tid  = threadIdx.x;
    const int warp = tid >> 5, lane = tid & 31;
    const int y  = blockIdx.x * 8 + warp;
    const int z0 = blockIdx.y * ZC;
    const int k  = blockIdx.z & 3;
    const int b  = blockIdx.z >> 2;
    const int bk = b*NK + k;
    const int x4 = lane * 4;

    const float Nf = (float)VOL;
    const float mean = (g_s.S1[bk] / Nf) / (g_s.S2[bk] / Nf + 1e-5f);

    const __half*  bp = g_blur + (size_t)bk * VOL + y * 128 + x4;
    const float4*  lp = (const float4*)(labels + (size_t)bk * VOL + y * 128 + x4);
    const float4*  ip = (const float4*)(inputs + (size_t)b  * VOL + y * 128 + x4);

    uint2 v[9];
    #pragma unroll
    for (int j = 0; j < 9; j++) {
        int zz = z0 - RAD + j;
        v[j] = (zz >= 0 && zz < DIMZ)
             ? *reinterpret_cast<const uint2*>(bp + (size_t)zz * HW)
             : make_uint2(0u, 0u);
    }

    float num = 0.f, den = 0.f;

    #pragma unroll 2
    for (int cz = 0; cz < ZC; cz++) {
        int z = z0 + cz;
        __half2 b0 = u2h(0u), b1 = u2h(0u);
        #pragma unroll
        for (int j = 0; j < 9; j++) {
            __half2 g = u2h(c_gh2[j]);
            b0 = __hfma2(g, u2h(v[j].x), b0);
            b1 = __hfma2(g, u2h(v[j].y), b1);
        }
        float2 f0 = __half22float2(b0);
        float2 f1 = __half22float2(b1);

        float4 lab = __ldcs(lp + (size_t)z * (HW/4));
        float4 inp = ip[(size_t)z * (HW/4)];

        {
            float d = inp.x - mean, d2 = d*d, wv = __expf(-d2*d2);
            num = fmaf(f0.x * lab.x, wv, num); den = fmaf(f0.x, wv, den);
        }
        {
            float d = inp.y - mean, d2 = d*d, wv = __expf(-d2*d2);
            num = fmaf(f0.y * lab.y, wv, num); den = fmaf(f0.y, wv, den);
        }
        {
            float d = inp.z - mean, d2 = d*d, wv = __expf(-d2*d2);
            num = fmaf(f1.x * lab.z, wv, num); den = fmaf(f1.x, wv, den);
        }
        {
            float d = inp.w - mean, d2 = d*d, wv = __expf(-d2*d2);
            num = fmaf(f1.y * lab.w, wv, num); den = fmaf(f1.y, wv, den);
        }

        #pragma unroll
        for (int j = 0; j < 8; j++) v[j] = v[j + 1];
        int zn = z + RAD + 1;
        v[8] = (zn < DIMZ)
             ? *reinterpret_cast<const uint2*>(bp + (size_t)zn * HW)
             : make_uint2(0u, 0u);
    }

    // CTA reduction -> 2 double atomics.
    #pragma unroll
    for (int o = 16; o; o >>= 1) {
        num += __shfl_down_sync(0xffffffffu, num, o);
        den += __shfl_down_sync(0xffffffffu, den, o);
    }
    __shared__ float rn[8], rd[8];
    if (lane == 0) { rn[warp] = num; rd[warp] = den; }
    __syncthreads();
    __shared__ bool is_last;
    if (tid == 0) {
        double a = 0.0, c = 0.0;
        #pragma unroll
        for (int w = 0; w < 8; w++) { a += (double)rn[w]; c += (double)rd[w]; }
        atomicAdd(&g_s.num[k], a);
        atomicAdd(&g_s.den[k], c);
        __threadfence();
        int done = atomicAdd(&g_s.ctr, 1);
        is_last = (done == K2_CTAS - 1);
    }
    __syncthreads();

    if (is_last && tid == 0) {
        __threadfence();
        float loss = 0.f;
        #pragma unroll
        for (int kk = 0; kk < NK; kk++) {
            float n = (float)g_s.num[kk];
            float d = (float)g_s.den[kk];
            loss += fabsf(n / (d + 1e-6f));
        }
        out[0] = (float)NK - loss;
    }
}

extern "C" void kernel_launch(void* const* d_in, const int* in_sizes, int n_in,
                              void* d_out, int out_size) {
    const float* labels;
    const float* inputs;
    if (in_sizes[0] == NB*NK*VOL) {
        labels = (const float*)d_in[0];
        inputs = (const float*)d_in[1];
    } else {
        labels = (const float*)d_in[1];
        inputs = (const float*)d_in[0];
    }

    void* scal_ptr = nullptr;
    cudaGetSymbolAddress(&scal_ptr, g_s);
    cudaMemsetAsync(scal_ptr, 0, sizeof(Scal));

    dim3 g1(64, 4, 2);
    k_xyblur<<<g1, 256>>>(labels, inputs);

    dim3 g2(16, 16, 8);
    k_zred<<<g2, 256>>>(labels, inputs, (float*)d_out);
}

// round 10
// speedup vs baseline: 1.0077x; 1.0077x over previous
#include <cuda_runtime.h>
#include <cuda_fp16.h>
#include <math.h>

#define DIMZ 128
#define HW   (128*128)
#define VOL  (128*128*128)
#define NB   2
#define NK   4
#define RAD  4
#define ZC   16                 // z-chunk in K2
#define K2_CTAS (16*8*8)        // ytiles * zchunks * (k*b)

// 32 MB fp16 scratch for the XY-blurred labels field.
__device__ __align__(16) __half g_blur[NB*NK*VOL];

struct Scal {
    float  S1[NB*NK];
    float  S2[NB*NK];
    double num[NK];
    double den[NK];
    int    ctr;
};
__device__ Scal g_s;

// gauss taps: exp(-x^2/(2*25)) for x=-4..4 (fp32, for x-blur + packing)
__constant__ float c_g[9] = {
    0.72614904f, 0.83527021f, 0.92311635f, 0.98019867f, 1.0f,
    0.98019867f, 0.92311635f, 0.83527021f, 0.72614904f
};
// same taps as packed half2 bit patterns (round-to-nearest fp16)
__constant__ unsigned c_gh2[9] = {
    0x39CF39CFu, 0x3AAF3AAFu, 0x3B633B63u, 0x3BD73BD7u, 0x3C003C00u,
    0x3BD73BD7u, 0x3B633B63u, 0x3AAF3AAFu, 0x39CF39CFu
};

__device__ __forceinline__ __half2 u2h(unsigned u) {
    return *reinterpret_cast<__half2*>(&u);
}
__device__ __forceinline__ unsigned h2u(__half2 h) {
    return *reinterpret_cast<unsigned*>(&h);
}

__device__ __forceinline__ float blur9(const float* a) {
    float acc = 0.f;
    #pragma unroll
    for (int t = 0; t < 9; t++) acc = fmaf(c_g[t], a[t], acc);
    return acc;
}

// Load labels row gy (zero outside volume), accumulate mean sums on uniquely
// owned center rows, return the X-blurred float4 for this lane (x = 4*lane)
// using lane shuffles for the +-4 halo. No shared memory.
__device__ __forceinline__ float4 xblur_load(
    int gy, const float4* __restrict__ lp4, const float4* __restrict__ ip4,
    int lane, int y0, float& s1, float& s2)
{
    float4 c = make_float4(0.f, 0.f, 0.f, 0.f);
    if (gy >= 0 && gy < 128) {
        c = __ldcs(lp4 + gy * 32 + lane);
        if (gy >= y0 && gy < y0 + 32) {
            float4 u = ip4[gy * 32 + lane];
            s1 += c.x*u.x + c.y*u.y + c.z*u.z + c.w*u.w;
            s2 += c.x + c.y + c.z + c.w;
        }
    }
    float a[12];
    a[0] = __shfl_up_sync(0xffffffffu, c.x, 1);
    a[1] = __shfl_up_sync(0xffffffffu, c.y, 1);
    a[2] = __shfl_up_sync(0xffffffffu, c.z, 1);
    a[3] = __shfl_up_sync(0xffffffffu, c.w, 1);
    if (lane == 0) { a[0] = a[1] = a[2] = a[3] = 0.f; }
    a[4] = c.x; a[5] = c.y; a[6] = c.z; a[7] = c.w;
    a[8]  = __shfl_down_sync(0xffffffffu, c.x, 1);
    a[9]  = __shfl_down_sync(0xffffffffu, c.y, 1);
    a[10] = __shfl_down_sync(0xffffffffu, c.z, 1);
    a[11] = __shfl_down_sync(0xffffffffu, c.w, 1);
    if (lane == 31) { a[8] = a[9] = a[10] = a[11] = 0.f; }
    float4 r;
    r.x = blur9(a + 0);
    r.y = blur9(a + 1);
    r.z = blur9(a + 2);
    r.w = blur9(a + 3);
    return r;
}

// Pack an fp32 x-blurred float4 into 2 half2 (uint2).
__device__ __forceinline__ uint2 pack4(float4 r) {
    uint2 p;
    p.x = h2u(__floats2half2_rn(r.x, r.y));
    p.y = h2u(__floats2half2_rn(r.z, r.w));
    return p;
}

// ---------------------------------------------------------------------------
// K1: XY blur of labels, register/shuffle resident. Y-ring held as packed
// half2; Y-blur in HFMA2.  (R6 body — best measured.)
// grid: (64 zpairs, 4 k, 2 b) x 256 thr; warp w -> z = 2*zg + (w>>2), yq = w&3.
// Fused: mean sums (sum p*inp, sum p) per (b,k).
// ---------------------------------------------------------------------------
__global__ __launch_bounds__(256)
void k_xyblur(const float* __restrict__ labels, const float* __restrict__ inputs) {
    const int tid = threadIdx.x;
    const int warp = tid >> 5, lane = tid & 31;
    const int z  = blockIdx.x * 2 + (warp >> 2);
    const int yq = warp & 3;
    const int y0 = yq * 32;
    const int k  = blockIdx.y;
    const int b  = blockIdx.z;
    const int x4 = lane * 4;

    const float4* lp4 = (const float4*)(labels + (size_t)(b*NK + k) * VOL + (size_t)z * HW);
    const float4* ip4 = (const float4*)(inputs + (size_t)b * VOL + (size_t)z * HW);
    __half* op = g_blur + (size_t)(b*NK + k) * VOL + (size_t)z * HW;

    float s1 = 0.f, s2 = 0.f;
    uint2 w[9];
    #pragma unroll
    for (int j = 0; j < 9; j++)
        w[j] = pack4(xblur_load(y0 - RAD + j, lp4, ip4, lane, y0, s1, s2));

    #pragma unroll 4
    for (int i = 0; i < 32; i++) {
        __half2 b0 = u2h(0u), b1 = u2h(0u);
        #pragma unroll
        for (int j = 0; j < 9; j++) {
            __half2 g = u2h(c_gh2[j]);
            b0 = __hfma2(g, u2h(w[j].x), b0);
            b1 = __hfma2(g, u2h(w[j].y), b1);
        }
        uint2 pk; pk.x = h2u(b0); pk.y = h2u(b1);
        *reinterpret_cast<uint2*>(op + (y0 + i) * 128 + x4) = pk;

        #pragma unroll
        for (int j = 0; j < 8; j++) w[j] = w[j + 1];
        w[8] = pack4(xblur_load(y0 + i + RAD + 1, lp4, ip4, lane, y0, s1, s2));
    }

    // Warp-reduce mean sums, then CTA-reduce -> 2 atomics per CTA.
    #pragma unroll
    for (int o = 16; o; o >>= 1) {
        s1 += __shfl_down_sync(0xffffffffu, s1, o);
        s2 += __shfl_down_sync(0xffffffffu, s2, o);
    }
    __shared__ float rs1[8], rs2[8];
    if (lane == 0) { rs1[warp] = s1; rs2[warp] = s2; }
    __syncthreads();
    if (tid == 0) {
        float a = 0.f, c = 0.f;
        #pragma unroll
        for (int ww = 0; ww < 8; ww++) { a += rs1[ww]; c += rs2[ww]; }
        atomicAdd(&g_s.S1[b*NK + k], a);
        atomicAdd(&g_s.S2[b*NK + k], c);
    }
}

// ---------------------------------------------------------------------------
// K2: Z blur with rolling half2 window (HFMA2), fused weights + reduction.
//     num = sum B(p)*p*w,  den = sum B(p)*w   (blur operator self-adjoint).
// R6 body + ZC=16; single new lever: launch_bounds(256,5) -> 5 CTAs/SM.
// grid: (16 ytiles, 8 zchunks, 8 = k + 4*b) x 256. Last CTA finalizes.
// ---------------------------------------------------------------------------
__global__ __launch_bounds__(256, 5)
void k_zred(const float* __restrict__ labels, const float* __restrict__ inputs,
            float* __restrict__ out) {
    const int tid  = threadIdx.x;
    const int warp = tid >> 5, lane = tid & 31;
    const int y  = blockIdx.x * 8 + warp;
    const int z0 = blockIdx.y * ZC;
    const int k  = blockIdx.z & 3;
    const int b  = blockIdx.z >> 2;
    const int bk = b*NK + k;
    const int x4 = lane * 4;

    const float Nf = (float)VOL;
    const float mean = (g_s.S1[bk] / Nf) / (g_s.S2[bk] / Nf + 1e-5f);

    const __half*  bp = g_blur + (size_t)bk * VOL + y * 128 + x4;
    const float4*  lp = (const float4*)(labels + (size_t)bk * VOL + y * 128 + x4);
    const float4*  ip = (const float4*)(inputs + (size_t)b  * VOL + y * 128 + x4);

    uint2 v[9];
    #pragma unroll
    for (int j = 0; j < 9; j++) {
        int zz = z0 - RAD + j;
        v[j] = (zz >= 0 && zz < DIMZ)
             ? *reinterpret_cast<const uint2*>(bp + (size_t)zz * HW)
             : make_uint2(0u, 0u);
    }

    float num = 0.f, den = 0.f;

    #pragma unroll 2
    for (int cz = 0; cz < ZC; cz++) {
        int z = z0 + cz;
        __half2 b0 = u2h(0u), b1 = u2h(0u);
        #pragma unroll
        for (int j = 0; j < 9; j++) {
            __half2 g = u2h(c_gh2[j]);
            b0 = __hfma2(g, u2h(v[j].x), b0);
            b1 = __hfma2(g, u2h(v[j].y), b1);
        }
        float2 f0 = __half22float2(b0);
        float2 f1 = __half22float2(b1);

        float4 lab = __ldcs(lp + (size_t)z * (HW/4));
        float4 inp = ip[(size_t)z * (HW/4)];

        {
            float d = inp.x - mean, d2 = d*d, wv = __expf(-d2*d2);
            num = fmaf(f0.x * lab.x, wv, num); den = fmaf(f0.x, wv, den);
        }
        {
            float d = inp.y - mean, d2 = d*d, wv = __expf(-d2*d2);
            num = fmaf(f0.y * lab.y, wv, num); den = fmaf(f0.y, wv, den);
        }
        {
            float d = inp.z - mean, d2 = d*d, wv = __expf(-d2*d2);
            num = fmaf(f1.x * lab.z, wv, num); den = fmaf(f1.x, wv, den);
        }
        {
            float d = inp.w - mean, d2 = d*d, wv = __expf(-d2*d2);
            num = fmaf(f1.y * lab.w, wv, num); den = fmaf(f1.y, wv, den);
        }

        #pragma unroll
        for (int j = 0; j < 8; j++) v[j] = v[j + 1];
        int zn = z + RAD + 1;
        v[8] = (zn < DIMZ)
             ? *reinterpret_cast<const uint2*>(bp + (size_t)zn * HW)
             : make_uint2(0u, 0u);
    }

    // CTA reduction -> 2 double atomics.
    #pragma unroll
    for (int o = 16; o; o >>= 1) {
        num += __shfl_down_sync(0xffffffffu, num, o);
        den += __shfl_down_sync(0xffffffffu, den, o);
    }
    __shared__ float rn[8], rd[8];
    if (lane == 0) { rn[warp] = num; rd[warp] = den; }
    __syncthreads();
    __shared__ bool is_last;
    if (tid == 0) {
        double a = 0.0, c = 0.0;
        #pragma unroll
        for (int w = 0; w < 8; w++) { a += (double)rn[w]; c += (double)rd[w]; }
        atomicAdd(&g_s.num[k], a);
        atomicAdd(&g_s.den[k], c);
        __threadfence();
        int done = atomicAdd(&g_s.ctr, 1);
        is_last = (done == K2_CTAS - 1);
    }
    __syncthreads();

    if (is_last && tid == 0) {
        __threadfence();
        float loss = 0.f;
        #pragma unroll
        for (int kk = 0; kk < NK; kk++) {
            float n = (float)g_s.num[kk];
            float d = (float)g_s.den[kk];
            loss += fabsf(n / (d + 1e-6f));
        }
        out[0] = (float)NK - loss;
    }
}

extern "C" void kernel_launch(void* const* d_in, const int* in_sizes, int n_in,
                              void* d_out, int out_size) {
    const float* labels;
    const float* inputs;
    if (in_sizes[0] == NB*NK*VOL) {
        labels = (const float*)d_in[0];
        inputs = (const float*)d_in[1];
    } else {
        labels = (const float*)d_in[1];
        inputs = (const float*)d_in[0];
    }

    void* scal_ptr = nullptr;
    cudaGetSymbolAddress(&scal_ptr, g_s);
    cudaMemsetAsync(scal_ptr, 0, sizeof(Scal));

    dim3 g1(64, 4, 2);
    k_xyblur<<<g1, 256>>>(labels, inputs);

    dim3 g2(16, 8, 8);
    k_zred<<<g2, 256>>>(labels, inputs, (float*)d_out);
}

// round 11
// speedup vs baseline: 1.1313x; 1.1226x over previous
#include <cuda_runtime.h>
#include <cuda_fp16.h>
#include <math.h>

#define DIMZ 128
#define HW   (128*128)
#define VOL  (128*128*128)
#define NB   2
#define NK   4
#define RAD  4
#define ZC   32                 // z-chunk in K2 (halo ratio 1.25 — R3's best shape)
#define K2_CTAS (16*4*8)        // ytiles * zchunks * (k*b)

// 32 MB fp16 scratch for the XY-blurred labels field.
__device__ __align__(16) __half g_blur[NB*NK*VOL];

struct Scal {
    float  S1[NB*NK];
    float  S2[NB*NK];
    double num[NK];
    double den[NK];
    int    ctr;
};
__device__ Scal g_s;

// gauss taps: exp(-x^2/(2*25)) for x=-4..4 (fp32, for x-blur + packing)
__constant__ float c_g[9] = {
    0.72614904f, 0.83527021f, 0.92311635f, 0.98019867f, 1.0f,
    0.98019867f, 0.92311635f, 0.83527021f, 0.72614904f
};
// same taps as packed half2 bit patterns (round-to-nearest fp16)
__constant__ unsigned c_gh2[9] = {
    0x39CF39CFu, 0x3AAF3AAFu, 0x3B633B63u, 0x3BD73BD7u, 0x3C003C00u,
    0x3BD73BD7u, 0x3B633B63u, 0x3AAF3AAFu, 0x39CF39CFu
};

__device__ __forceinline__ __half2 u2h(unsigned u) {
    return *reinterpret_cast<__half2*>(&u);
}
__device__ __forceinline__ unsigned h2u(__half2 h) {
    return *reinterpret_cast<unsigned*>(&h);
}

__device__ __forceinline__ float blur9(const float* a) {
    float acc = 0.f;
    #pragma unroll
    for (int t = 0; t < 9; t++) acc = fmaf(c_g[t], a[t], acc);
    return acc;
}

// Load labels row gy (zero outside volume), accumulate mean sums on uniquely
// owned center rows, return the X-blurred float4 for this lane (x = 4*lane)
// using lane shuffles for the +-4 halo. No shared memory.
__device__ __forceinline__ float4 xblur_load(
    int gy, const float4* __restrict__ lp4, const float4* __restrict__ ip4,
    int lane, int y0, float& s1, float& s2)
{
    float4 c = make_float4(0.f, 0.f, 0.f, 0.f);
    if (gy >= 0 && gy < 128) {
        c = __ldcs(lp4 + gy * 32 + lane);
        if (gy >= y0 && gy < y0 + 32) {
            float4 u = ip4[gy * 32 + lane];
            s1 += c.x*u.x + c.y*u.y + c.z*u.z + c.w*u.w;
            s2 += c.x + c.y + c.z + c.w;
        }
    }
    float a[12];
    a[0] = __shfl_up_sync(0xffffffffu, c.x, 1);
    a[1] = __shfl_up_sync(0xffffffffu, c.y, 1);
    a[2] = __shfl_up_sync(0xffffffffu, c.z, 1);
    a[3] = __shfl_up_sync(0xffffffffu, c.w, 1);
    if (lane == 0) { a[0] = a[1] = a[2] = a[3] = 0.f; }
    a[4] = c.x; a[5] = c.y; a[6] = c.z; a[7] = c.w;
    a[8]  = __shfl_down_sync(0xffffffffu, c.x, 1);
    a[9]  = __shfl_down_sync(0xffffffffu, c.y, 1);
    a[10] = __shfl_down_sync(0xffffffffu, c.z, 1);
    a[11] = __shfl_down_sync(0xffffffffu, c.w, 1);
    if (lane == 31) { a[8] = a[9] = a[10] = a[11] = 0.f; }
    float4 r;
    r.x = blur9(a + 0);
    r.y = blur9(a + 1);
    r.z = blur9(a + 2);
    r.w = blur9(a + 3);
    return r;
}

// Pack an fp32 x-blurred float4 into 2 half2 (uint2).
__device__ __forceinline__ uint2 pack4(float4 r) {
    uint2 p;
    p.x = h2u(__floats2half2_rn(r.x, r.y));
    p.y = h2u(__floats2half2_rn(r.z, r.w));
    return p;
}

// ---------------------------------------------------------------------------
// K1: XY blur of labels, register/shuffle resident. Y-ring held as packed
// half2; Y-blur in HFMA2.  (R6 body — best measured; untouched.)
// grid: (64 zpairs, 4 k, 2 b) x 256 thr; warp w -> z = 2*zg + (w>>2), yq = w&3.
// Fused: mean sums (sum p*inp, sum p) per (b,k).
// ---------------------------------------------------------------------------
__global__ __launch_bounds__(256)
void k_xyblur(const float* __restrict__ labels, const float* __restrict__ inputs) {
    const int tid = threadIdx.x;
    const int warp = tid >> 5, lane = tid & 31;
    const int z  = blockIdx.x * 2 + (warp >> 2);
    const int yq = warp & 3;
    const int y0 = yq * 32;
    const int k  = blockIdx.y;
    const int b  = blockIdx.z;
    const int x4 = lane * 4;

    const float4* lp4 = (const float4*)(labels + (size_t)(b*NK + k) * VOL + (size_t)z * HW);
    const float4* ip4 = (const float4*)(inputs + (size_t)b * VOL + (size_t)z * HW);
    __half* op = g_blur + (size_t)(b*NK + k) * VOL + (size_t)z * HW;

    float s1 = 0.f, s2 = 0.f;
    uint2 w[9];
    #pragma unroll
    for (int j = 0; j < 9; j++)
        w[j] = pack4(xblur_load(y0 - RAD + j, lp4, ip4, lane, y0, s1, s2));

    #pragma unroll 4
    for (int i = 0; i < 32; i++) {
        __half2 b0 = u2h(0u), b1 = u2h(0u);
        #pragma unroll
        for (int j = 0; j < 9; j++) {
            __half2 g = u2h(c_gh2[j]);
            b0 = __hfma2(g, u2h(w[j].x), b0);
            b1 = __hfma2(g, u2h(w[j].y), b1);
        }
        uint2 pk; pk.x = h2u(b0); pk.y = h2u(b1);
        *reinterpret_cast<uint2*>(op + (y0 + i) * 128 + x4) = pk;

        #pragma unroll
        for (int j = 0; j < 8; j++) w[j] = w[j + 1];
        w[8] = pack4(xblur_load(y0 + i + RAD + 1, lp4, ip4, lane, y0, s1, s2));
    }

    // Warp-reduce mean sums, then CTA-reduce -> 2 atomics per CTA.
    #pragma unroll
    for (int o = 16; o; o >>= 1) {
        s1 += __shfl_down_sync(0xffffffffu, s1, o);
        s2 += __shfl_down_sync(0xffffffffu, s2, o);
    }
    __shared__ float rs1[8], rs2[8];
    if (lane == 0) { rs1[warp] = s1; rs2[warp] = s2; }
    __syncthreads();
    if (tid == 0) {
        float a = 0.f, c = 0.f;
        #pragma unroll
        for (int ww = 0; ww < 8; ww++) { a += rs1[ww]; c += rs2[ww]; }
        atomicAdd(&g_s.S1[b*NK + k], a);
        atomicAdd(&g_s.S2[b*NK + k], c);
    }
}

// ---------------------------------------------------------------------------
// K2: Z blur with rolling half2 window (HFMA2), fused weights + reduction.
//     num = sum B(p)*p*w,  den = sum B(p)*w   (blur operator self-adjoint).
// R6 body; ZC=32 (R3's best shape) + fully-unrolled z loop so the 9-wide
// ring is register-renamed instead of MOV-shifted. No launch_bounds cap.
// grid: (16 ytiles, 4 zchunks, 8 = k + 4*b) x 256. Last CTA finalizes.
// ---------------------------------------------------------------------------
__global__ __launch_bounds__(256)
void k_zred(const float* __restrict__ labels, const float* __restrict__ inputs,
            float* __restrict__ out) {
    const int tid  = threadIdx.x;
    const int warp = tid >> 5, lane = tid & 31;
    const int y  = blockIdx.x * 8 + warp;
    const int z0 = blockIdx.y * ZC;
    const int k  = blockIdx.z & 3;
    const int b  = blockIdx.z >> 2;
    const int bk = b*NK + k;
    const int x4 = lane * 4;

    const float Nf = (float)VOL;
    const float mean = (g_s.S1[bk] / Nf) / (g_s.S2[bk] / Nf + 1e-5f);

    const __half*  bp = g_blur + (size_t)bk * VOL + y * 128 + x4;
    const float4*  lp = (const float4*)(labels + (size_t)bk * VOL + y * 128 + x4);
    const float4*  ip = (const float4*)(inputs + (size_t)b  * VOL + y * 128 + x4);

    uint2 v[9];
    #pragma unroll
    for (int j = 0; j < 9; j++) {
        int zz = z0 - RAD + j;
        v[j] = (zz >= 0 && zz < DIMZ)
             ? *reinterpret_cast<const uint2*>(bp + (size_t)zz * HW)
             : make_uint2(0u, 0u);
    }

    float num = 0.f, den = 0.f;

    #pragma unroll
    for (int cz = 0; cz < ZC; cz++) {
        int z = z0 + cz;
        __half2 b0 = u2h(0u), b1 = u2h(0u);
        #pragma unroll
        for (int j = 0; j < 9; j++) {
            __half2 g = u2h(c_gh2[j]);
            b0 = __hfma2(g, u2h(v[j].x), b0);
            b1 = __hfma2(g, u2h(v[j].y), b1);
        }
        float2 f0 = __half22float2(b0);
        float2 f1 = __half22float2(b1);

        float4 lab = __ldcs(lp + (size_t)z * (HW/4));
        float4 inp = ip[(size_t)z * (HW/4)];

        {
            float d = inp.x - mean, d2 = d*d, wv = __expf(-d2*d2);
            num = fmaf(f0.x * lab.x, wv, num); den = fmaf(f0.x, wv, den);
        }
        {
            float d = inp.y - mean, d2 = d*d, wv = __expf(-d2*d2);
            num = fmaf(f0.y * lab.y, wv, num); den = fmaf(f0.y, wv, den);
        }
        {
            float d = inp.z - mean, d2 = d*d, wv = __expf(-d2*d2);
            num = fmaf(f1.x * lab.z, wv, num); den = fmaf(f1.x, wv, den);
        }
        {
            float d = inp.w - mean, d2 = d*d, wv = __expf(-d2*d2);
            num = fmaf(f1.y * lab.w, wv, num); den = fmaf(f1.y, wv, den);
        }

        #pragma unroll
        for (int j = 0; j < 8; j++) v[j] = v[j + 1];
        int zn = z + RAD + 1;
        v[8] = (zn < DIMZ)
             ? *reinterpret_cast<const uint2*>(bp + (size_t)zn * HW)
             : make_uint2(0u, 0u);
    }

    // CTA reduction -> 2 double atomics.
    #pragma unroll
    for (int o = 16; o; o >>= 1) {
        num += __shfl_down_sync(0xffffffffu, num, o);
        den += __shfl_down_sync(0xffffffffu, den, o);
    }
    __shared__ float rn[8], rd[8];
    if (lane == 0) { rn[warp] = num; rd[warp] = den; }
    __syncthreads();
    __shared__ bool is_last;
    if (tid == 0) {
        double a = 0.0, c = 0.0;
        #pragma unroll
        for (int w = 0; w < 8; w++) { a += (double)rn[w]; c += (double)rd[w]; }
        atomicAdd(&g_s.num[k], a);
        atomicAdd(&g_s.den[k], c);
        __threadfence();
        int done = atomicAdd(&g_s.ctr, 1);
        is_last = (done == K2_CTAS - 1);
    }
    __syncthreads();

    if (is_last && tid == 0) {
        __threadfence();
        float loss = 0.f;
        #pragma unroll
        for (int kk = 0; kk < NK; kk++) {
            float n = (float)g_s.num[kk];
            float d = (float)g_s.den[kk];
            loss += fabsf(n / (d + 1e-6f));
        }
        out[0] = (float)NK - loss;
    }
}

extern "C" void kernel_launch(void* const* d_in, const int* in_sizes, int n_in,
                              void* d_out, int out_size) {
    const float* labels;
    const float* inputs;
    if (in_sizes[0] == NB*NK*VOL) {
        labels = (const float*)d_in[0];
        inputs = (const float*)d_in[1];
    } else {
        labels = (const float*)d_in[1];
        inputs = (const float*)d_in[0];
    }

    void* scal_ptr = nullptr;
    cudaGetSymbolAddress(&scal_ptr, g_s);
    cudaMemsetAsync(scal_ptr, 0, sizeof(Scal));

    dim3 g1(64, 4, 2);
    k_xyblur<<<g1, 256>>>(labels, inputs);

    dim3 g2(16, 4, 8);
    k_zred<<<g2, 256>>>(labels, inputs, (float*)d_out);
}

// round 12
// speedup vs baseline: 1.1549x; 1.0209x over previous
#include <cuda_runtime.h>
#include <cuda_fp16.h>
#include <math.h>

#define DIMZ 128
#define HW   (128*128)
#define VOL  (128*128*128)
#define NB   2
#define NK   4
#define RAD  4
#define ZC   32                 // z-chunk in K2 (halo ratio 1.25)
#define K2_CTAS (32*4*8)        // ytiles * zchunks * (k*b)

// 32 MB fp16 scratch for the XY-blurred labels field.
__device__ __align__(16) __half g_blur[NB*NK*VOL];

struct Scal {
    float  S1[NB*NK];
    float  S2[NB*NK];
    double num[NK];
    double den[NK];
    int    ctr;
};
__device__ Scal g_s;

// gauss taps: exp(-x^2/(2*25)) for x=-4..4 (fp32, for x-blur + packing)
__constant__ float c_g[9] = {
    0.72614904f, 0.83527021f, 0.92311635f, 0.98019867f, 1.0f,
    0.98019867f, 0.92311635f, 0.83527021f, 0.72614904f
};
// same taps as packed half2 bit patterns (round-to-nearest fp16)
__constant__ unsigned c_gh2[9] = {
    0x39CF39CFu, 0x3AAF3AAFu, 0x3B633B63u, 0x3BD73BD7u, 0x3C003C00u,
    0x3BD73BD7u, 0x3B633B63u, 0x3AAF3AAFu, 0x39CF39CFu
};

__device__ __forceinline__ __half2 u2h(unsigned u) {
    return *reinterpret_cast<__half2*>(&u);
}
__device__ __forceinline__ unsigned h2u(__half2 h) {
    return *reinterpret_cast<unsigned*>(&h);
}

__device__ __forceinline__ float blur9(const float* a) {
    float acc = 0.f;
    #pragma unroll
    for (int t = 0; t < 9; t++) acc = fmaf(c_g[t], a[t], acc);
    return acc;
}

// Load labels row gy (zero outside volume), accumulate mean sums on uniquely
// owned center rows, return the X-blurred float4 for this lane (x = 4*lane)
// using lane shuffles for the +-4 halo. No shared memory.
__device__ __forceinline__ float4 xblur_load(
    int gy, const float4* __restrict__ lp4, const float4* __restrict__ ip4,
    int lane, int y0, float& s1, float& s2)
{
    float4 c = make_float4(0.f, 0.f, 0.f, 0.f);
    if (gy >= 0 && gy < 128) {
        c = __ldcs(lp4 + gy * 32 + lane);
        if (gy >= y0 && gy < y0 + 32) {
            float4 u = ip4[gy * 32 + lane];
            s1 += c.x*u.x + c.y*u.y + c.z*u.z + c.w*u.w;
            s2 += c.x + c.y + c.z + c.w;
        }
    }
    float a[12];
    a[0] = __shfl_up_sync(0xffffffffu, c.x, 1);
    a[1] = __shfl_up_sync(0xffffffffu, c.y, 1);
    a[2] = __shfl_up_sync(0xffffffffu, c.z, 1);
    a[3] = __shfl_up_sync(0xffffffffu, c.w, 1);
    if (lane == 0) { a[0] = a[1] = a[2] = a[3] = 0.f; }
    a[4] = c.x; a[5] = c.y; a[6] = c.z; a[7] = c.w;
    a[8]  = __shfl_down_sync(0xffffffffu, c.x, 1);
    a[9]  = __shfl_down_sync(0xffffffffu, c.y, 1);
    a[10] = __shfl_down_sync(0xffffffffu, c.z, 1);
    a[11] = __shfl_down_sync(0xffffffffu, c.w, 1);
    if (lane == 31) { a[8] = a[9] = a[10] = a[11] = 0.f; }
    float4 r;
    r.x = blur9(a + 0);
    r.y = blur9(a + 1);
    r.z = blur9(a + 2);
    r.w = blur9(a + 3);
    return r;
}

// Pack an fp32 x-blurred float4 into 2 half2 (uint2).
__device__ __forceinline__ uint2 pack4(float4 r) {
    uint2 p;
    p.x = h2u(__floats2half2_rn(r.x, r.y));
    p.y = h2u(__floats2half2_rn(r.z, r.w));
    return p;
}

// ---------------------------------------------------------------------------
// K1: XY blur of labels, register/shuffle resident; body unchanged from the
// measured optimum. Launch shape refined: CTA = 128 thr = 4 warps = the 4
// y-quarters of ONE z-slice. grid: (128 z, 4 k, 2 b) = 1024 CTAs.
// Fused: mean sums (sum p*inp, sum p) per (b,k).
// ---------------------------------------------------------------------------
__global__ __launch_bounds__(128)
void k_xyblur(const float* __restrict__ labels, const float* __restrict__ inputs) {
    const int tid = threadIdx.x;
    const int warp = tid >> 5, lane = tid & 31;
    const int z  = blockIdx.x;
    const int y0 = warp * 32;
    const int k  = blockIdx.y;
    const int b  = blockIdx.z;
    const int x4 = lane * 4;

    const float4* lp4 = (const float4*)(labels + (size_t)(b*NK + k) * VOL + (size_t)z * HW);
    const float4* ip4 = (const float4*)(inputs + (size_t)b * VOL + (size_t)z * HW);
    __half* op = g_blur + (size_t)(b*NK + k) * VOL + (size_t)z * HW;

    float s1 = 0.f, s2 = 0.f;
    uint2 w[9];
    #pragma unroll
    for (int j = 0; j < 9; j++)
        w[j] = pack4(xblur_load(y0 - RAD + j, lp4, ip4, lane, y0, s1, s2));

    #pragma unroll 4
    for (int i = 0; i < 32; i++) {
        __half2 b0 = u2h(0u), b1 = u2h(0u);
        #pragma unroll
        for (int j = 0; j < 9; j++) {
            __half2 g = u2h(c_gh2[j]);
            b0 = __hfma2(g, u2h(w[j].x), b0);
            b1 = __hfma2(g, u2h(w[j].y), b1);
        }
        uint2 pk; pk.x = h2u(b0); pk.y = h2u(b1);
        *reinterpret_cast<uint2*>(op + (y0 + i) * 128 + x4) = pk;

        #pragma unroll
        for (int j = 0; j < 8; j++) w[j] = w[j + 1];
        w[8] = pack4(xblur_load(y0 + i + RAD + 1, lp4, ip4, lane, y0, s1, s2));
    }

    // Warp-reduce mean sums, then CTA-reduce -> 2 atomics per CTA.
    #pragma unroll
    for (int o = 16; o; o >>= 1) {
        s1 += __shfl_down_sync(0xffffffffu, s1, o);
        s2 += __shfl_down_sync(0xffffffffu, s2, o);
    }
    __shared__ float rs1[4], rs2[4];
    if (lane == 0) { rs1[warp] = s1; rs2[warp] = s2; }
    __syncthreads();
    if (tid == 0) {
        float a = 0.f, c = 0.f;
        #pragma unroll
        for (int ww = 0; ww < 4; ww++) { a += rs1[ww]; c += rs2[ww]; }
        atomicAdd(&g_s.S1[b*NK + k], a);
        atomicAdd(&g_s.S2[b*NK + k], c);
    }
}

// ---------------------------------------------------------------------------
// K2: Z blur with rolling half2 window (HFMA2), fused weights + reduction.
//     num = sum B(p)*p*w,  den = sum B(p)*w   (blur operator self-adjoint).
// Body unchanged (fully-unrolled ZC=32). Launch shape refined: CTA = 128 thr
// = 4 warps = 4 y-rows. grid: (32 ytiles, 4 zchunks, 8 = k+4b) = 1024 CTAs.
// Last CTA finalizes.
// ---------------------------------------------------------------------------
__global__ __launch_bounds__(128)
void k_zred(const float* __restrict__ labels, const float* __restrict__ inputs,
            float* __restrict__ out) {
    const int tid  = threadIdx.x;
    const int warp = tid >> 5, lane = tid & 31;
    const int y  = blockIdx.x * 4 + warp;
    const int z0 = blockIdx.y * ZC;
    const int k  = blockIdx.z & 3;
    const int b  = blockIdx.z >> 2;
    const int bk = b*NK + k;
    const int x4 = lane * 4;

    const float Nf = (float)VOL;
    const float mean = (g_s.S1[bk] / Nf) / (g_s.S2[bk] / Nf + 1e-5f);

    const __half*  bp = g_blur + (size_t)bk * VOL + y * 128 + x4;
    const float4*  lp = (const float4*)(labels + (size_t)bk * VOL + y * 128 + x4);
    const float4*  ip = (const float4*)(inputs + (size_t)b  * VOL + y * 128 + x4);

    uint2 v[9];
    #pragma unroll
    for (int j = 0; j < 9; j++) {
        int zz = z0 - RAD + j;
        v[j] = (zz >= 0 && zz < DIMZ)
             ? *reinterpret_cast<const uint2*>(bp + (size_t)zz * HW)
             : make_uint2(0u, 0u);
    }

    float num = 0.f, den = 0.f;

    #pragma unroll
    for (int cz = 0; cz < ZC; cz++) {
        int z = z0 + cz;
        __half2 b0 = u2h(0u), b1 = u2h(0u);
        #pragma unroll
        for (int j = 0; j < 9; j++) {
            __half2 g = u2h(c_gh2[j]);
            b0 = __hfma2(g, u2h(v[j].x), b0);
            b1 = __hfma2(g, u2h(v[j].y), b1);
        }
        float2 f0 = __half22float2(b0);
        float2 f1 = __half22float2(b1);

        float4 lab = __ldcs(lp + (size_t)z * (HW/4));
        float4 inp = ip[(size_t)z * (HW/4)];

        {
            float d = inp.x - mean, d2 = d*d, wv = __expf(-d2*d2);
            num = fmaf(f0.x * lab.x, wv, num); den = fmaf(f0.x, wv, den);
        }
        {
            float d = inp.y - mean, d2 = d*d, wv = __expf(-d2*d2);
            num = fmaf(f0.y * lab.y, wv, num); den = fmaf(f0.y, wv, den);
        }
        {
            float d = inp.z - mean, d2 = d*d, wv = __expf(-d2*d2);
            num = fmaf(f1.x * lab.z, wv, num); den = fmaf(f1.x, wv, den);
        }
        {
            float d = inp.w - mean, d2 = d*d, wv = __expf(-d2*d2);
            num = fmaf(f1.y * lab.w, wv, num); den = fmaf(f1.y, wv, den);
        }

        #pragma unroll
        for (int j = 0; j < 8; j++) v[j] = v[j + 1];
        int zn = z + RAD + 1;
        v[8] = (zn < DIMZ)
             ? *reinterpret_cast<const uint2*>(bp + (size_t)zn * HW)
             : make_uint2(0u, 0u);
    }

    // CTA reduction -> 2 double atomics.
    #pragma unroll
    for (int o = 16; o; o >>= 1) {
        num += __shfl_down_sync(0xffffffffu, num, o);
        den += __shfl_down_sync(0xffffffffu, den, o);
    }
    __shared__ float rn[4], rd[4];
    if (lane == 0) { rn[warp] = num; rd[warp] = den; }
    __syncthreads();
    __shared__ bool is_last;
    if (tid == 0) {
        double a = 0.0, c = 0.0;
        #pragma unroll
        for (int w = 0; w < 4; w++) { a += (double)rn[w]; c += (double)rd[w]; }
        atomicAdd(&g_s.num[k], a);
        atomicAdd(&g_s.den[k], c);
        __threadfence();
        int done = atomicAdd(&g_s.ctr, 1);
        is_last = (done == K2_CTAS - 1);
    }
    __syncthreads();

    if (is_last && tid == 0) {
        __threadfence();
        float loss = 0.f;
        #pragma unroll
        for (int kk = 0; kk < NK; kk++) {
            float n = (float)g_s.num[kk];
            float d = (float)g_s.den[kk];
            loss += fabsf(n / (d + 1e-6f));
        }
        out[0] = (float)NK - loss;
    }
}

extern "C" void kernel_launch(void* const* d_in, const int* in_sizes, int n_in,
                              void* d_out, int out_size) {
    const float* labels;
    const float* inputs;
    if (in_sizes[0] == NB*NK*VOL) {
        labels = (const float*)d_in[0];
        inputs = (const float*)d_in[1];
    } else {
        labels = (const float*)d_in[1];
        inputs = (const float*)d_in[0];
    }

    void* scal_ptr = nullptr;
    cudaGetSymbolAddress(&scal_ptr, g_s);
    cudaMemsetAsync(scal_ptr, 0, sizeof(Scal));

    dim3 g1(128, 4, 2);
    k_xyblur<<<g1, 128>>>(labels, inputs);

    dim3 g2(32, 4, 8);
    k_zred<<<g2, 128>>>(labels, inputs, (float*)d_out);
}